// round 15
// baseline (speedup 1.0000x reference)
#include <cuda_runtime.h>

// Fused kernel: grouped 1x1 convs (q,k,v) + per-channel 5x5 windowed softmax,
// single pass, no global intermediate.
//   x : (2, 128, 96, 96) f32, w{q,k,v} : (4, 32, 32) f32, K=5 reflect pad 2.
#define BB    2
#define GG    4
#define HHN   96
#define WWN   96
#define HWSZ  (HHN * WWN)

#define OCPC   8      // output channels per CTA
#define STRIPS 6      // h strips of 16 output rows
#define SROWS  16
#define KRS    104    // k/v ring row stride (2 halo + 96 + 2 halo + pad), 416B = 16B-aligned

// Dynamic smem layout (floats):
//   ks   [OCPC][5][KRS]  = 4160
//   vs   [OCPC][5][KRS]  = 4160
//   xs   [2][32][96]     = 6144   (double-buffered input rows)
//   qr   [OCPC][3][96]   = 2304   (q ring)
//   wall [OCPC][33] f4   = 1056   (packed wq,wk,wv per (och,ich))
#define SMEM_FLOATS (4160 + 4160 + 6144 + 2304 + 1056)

__device__ __forceinline__ float ex2(float x) {
    float y;
    asm("ex2.approx.ftz.f32 %0, %1;" : "=f"(y) : "f"(x));
    return y;
}

extern __shared__ float smem[];

__global__ void __launch_bounds__(256) fused_kernel(
    const float* __restrict__ x,
    const float* __restrict__ wq,
    const float* __restrict__ wk,
    const float* __restrict__ wv,
    float* __restrict__ out)
{
    float*  ks   = smem;
    float*  vs   = ks + OCPC * 5 * KRS;
    float*  xs   = vs + OCPC * 5 * KRS;
    float*  qr   = xs + 2 * 32 * 96;
    float4* wall = reinterpret_cast<float4*>(qr + OCPC * 3 * 96);

    const int strip = blockIdx.x;              // 0..5
    const int ogrp  = blockIdx.y;              // 0..3 (8-channel group)
    const int bg    = blockIdx.z;              // b*4+g, 0..7
    const int g     = bg & 3;
    const int tid   = threadIdx.x;
    const int oc    = tid >> 5;                // 0..7 local output channel
    const int lane  = tid & 31;
    const int w3    = lane * 3;                // kv-phase: 3 w positions

    // Stage packed weights: one entry per thread. w[g][o][i], o = ogrp*8+oc.
    {
        int widx = g * 1024 + (ogrp * 8 + oc) * 32 + lane;
        wall[oc * 33 + lane] = make_float4(wq[widx], wk[widx], wv[widx], 0.f);
    }

    // x staging: 768 float4 per row, 3 per thread (precomputed mapping).
    const size_t xchan = (size_t)bg * 32 * HWSZ;
    const int ia = tid, ib = tid + 256, ic = tid + 512;
    const float* pa = x + xchan + (size_t)(ia / 24) * HWSZ + (ia % 24) * 4;
    const float* pb = x + xchan + (size_t)(ib / 24) * HWSZ + (ib % 24) * 4;
    const float* pc = x + xchan + (size_t)(ic / 24) * HWSZ + (ic % 24) * 4;

    const int h0 = strip * SROWS, h1 = h0 + SROWS;
    const int rlo = (h0 - 2 < 0) ? 0 : h0 - 2;
    const int kv_hi = (h1 + 1 > 95) ? 95 : h1 + 1;
    const float L2E = 1.44269504088896341f;

    __syncthreads();   // weights staged

    for (int r = rlo; r <= h1 + 2; ++r) {
        // --- Phase 1: issue global loads for x row r (consumed next iter) ---
        float4 xa, xb, xc;
        const bool do_stage = (r <= kv_hi);
        if (do_stage) {
            xa = *reinterpret_cast<const float4*>(pa + r * 96);
            xb = *reinterpret_cast<const float4*>(pb + r * 96);
            xc = *reinterpret_cast<const float4*>(pc + r * 96);
        }

        // --- Phase 2: compute k/v/q for row r-1 from xs[(r-1)&1] ---
        if (r - 1 >= rlo && r - 1 <= kv_hi) {
            const float* xrow = xs + ((r - 1) & 1) * 3072;
            float aq0 = 0.f, aq1 = 0.f, aq2 = 0.f;
            float ak0 = 0.f, ak1 = 0.f, ak2 = 0.f;
            float av0 = 0.f, av1 = 0.f, av2 = 0.f;
            #pragma unroll 8
            for (int i = 0; i < 32; i++) {
                const float4 w4 = wall[oc * 33 + i];          // broadcast LDS.128
                const float x0 = xrow[i * 96 + w3];
                const float x1 = xrow[i * 96 + w3 + 1];
                const float x2 = xrow[i * 96 + w3 + 2];
                aq0 = fmaf(x0, w4.x, aq0); aq1 = fmaf(x1, w4.x, aq1); aq2 = fmaf(x2, w4.x, aq2);
                ak0 = fmaf(x0, w4.y, ak0); ak1 = fmaf(x1, w4.y, ak1); ak2 = fmaf(x2, w4.y, ak2);
                av0 = fmaf(x0, w4.z, av0); av1 = fmaf(x1, w4.z, av1); av2 = fmaf(x2, w4.z, av2);
            }
            const int slot = (r - 1) % 5;
            float* kd = ks + oc * (5 * KRS) + slot * KRS;
            float* vd = vs + oc * (5 * KRS) + slot * KRS;
            kd[2 + w3] = ak0; kd[3 + w3] = ak1; kd[4 + w3] = ak2;
            vd[2 + w3] = av0; vd[3 + w3] = av1; vd[4 + w3] = av2;
            // w-reflect halo mirrors, written from registers (no extra barrier):
            if (lane == 0)  { kd[1]  = ak1; kd[0]  = ak2; vd[1]  = av1; vd[0]  = av2; }  // w=1,2
            if (lane == 31) { kd[99] = ak0; kd[98] = ak1; vd[99] = av0; vd[98] = av1; }  // w=93,94
            float* qd = qr + oc * 288 + ((r - 1) % 3) * 96;
            qd[w3] = aq0; qd[w3 + 1] = aq1; qd[w3 + 2] = aq2;
        }
        __syncthreads();   // kv ring + q ring ready

        // --- Phase 3: attention for output row r-3 (R10-proven inner loop) ---
        const int ot = r - 3;
        if (ot >= h0 && ot < h1 && lane < 24) {
            const int w0 = lane * 4;
            const float4 q4 = *reinterpret_cast<const float4*>(qr + oc * 288 + (ot % 3) * 96 + w0);
            float ql2[4] = { q4.x * L2E, q4.y * L2E, q4.z * L2E, q4.w * L2E };
            float num[4] = {0.f, 0.f, 0.f, 0.f};
            float den[4] = {0.f, 0.f, 0.f, 0.f};
            #pragma unroll
            for (int j = 0; j < 5; j++) {
                int rr = ot - 2 + j;
                rr = rr < 0 ? -rr : (rr > 95 ? 190 - rr : rr);   // h reflect
                const int so = oc * (5 * KRS) + (rr % 5) * KRS + w0;
                const float4* kp = reinterpret_cast<const float4*>(ks + so);
                const float4* vp = reinterpret_cast<const float4*>(vs + so);
                float4 k0 = kp[0], k1 = kp[1];
                float4 v0 = vp[0], v1 = vp[1];
                float kk[8] = { k0.x, k0.y, k0.z, k0.w, k1.x, k1.y, k1.z, k1.w };
                float vv[8] = { v0.x, v0.y, v0.z, v0.w, v1.x, v1.y, v1.z, v1.w };
                #pragma unroll
                for (int o = 0; o < 4; o++) {
                    #pragma unroll
                    for (int c = 0; c < 5; c++) {
                        float e = ex2(ql2[o] * kk[o + c]);
                        den[o] += e;
                        num[o] = fmaf(e, vv[o + c], num[o]);
                    }
                }
            }
            float4 r4 = make_float4(__fdividef(num[0], den[0]),
                                    __fdividef(num[1], den[1]),
                                    __fdividef(num[2], den[2]),
                                    __fdividef(num[3], den[3]));
            *reinterpret_cast<float4*>(
                out + ((size_t)bg * 32 + ogrp * 8 + oc) * HWSZ + (size_t)ot * 96 + w0) = r4;
        }

        // --- Phase 4: commit staged x row r to xs[r&1] ---
        if (do_stage) {
            float4* xd = reinterpret_cast<float4*>(xs + (r & 1) * 3072);
            xd[ia] = xa; xd[ib] = xb; xd[ic] = xc;
        }
        __syncthreads();   // xs[r&1] ready; ring/q slots free for reuse
    }
}

// Raise the dynamic-smem limit once, host-side, before any launch/capture.
static const bool g_attr_init = []() {
    cudaFuncSetAttribute(fused_kernel,
                         cudaFuncAttributeMaxDynamicSharedMemorySize,
                         SMEM_FLOATS * 4);
    return true;
}();

extern "C" void kernel_launch(void* const* d_in, const int* in_sizes, int n_in,
                              void* d_out, int out_size)
{
    const float* x  = (const float*)d_in[0];
    const float* wq = (const float*)d_in[1];
    const float* wk = (const float*)d_in[2];
    const float* wv = (const float*)d_in[3];
    float* out = (float*)d_out;
    (void)g_attr_init;

    fused_kernel<<<dim3(STRIPS, 4, BB * GG), 256, SMEM_FLOATS * 4>>>(
        x, wq, wk, wv, out);
}

// round 16
// speedup vs baseline: 1.6383x; 1.6383x over previous
#include <cuda_runtime.h>

// Problem constants (fixed shapes from reference):
//   x : (2, 128, 96, 96) f32, w{q,k,v} : (4, 32, 32) f32
//   K = 5 window, reflect pad 2, G = 4 groups of 32 channels.
#define BB   2
#define GG   4
#define CIN  32
#define CON  32
#define HHN  96
#define WWN  96
#define HWSZ (HHN * WWN)
#define CTOT 128

// Scratch for the three 1x1-conv outputs (q, k, v), each (B, 128, 96, 96).
// g_q holds q PRE-SCALED by log2(e) (folded into wq at weight staging).
__device__ __align__(256) float g_q[BB * CTOT * HWSZ];
__device__ __align__(256) float g_k[BB * CTOT * HWSZ];
__device__ __align__(256) float g_v[BB * CTOT * HWSZ];

// -----------------------------------------------------------------------------
// Kernel A: grouped 1x1 convs (q, k, v) fused — one CTA per (b, g, h) row.
// R10 config (best measured, ~18.1us): scalar FFMA, float4 x staging,
// __launch_bounds__(256,2), direct stores. Only change vs R10: wq is scaled
// by log2(e) during staging (free — weights load once per CTA), so attn can
// feed q straight into ex2 without a per-thread multiply.
// Ledger of regressions: plain bounds (20.0us), f32x2, smem-bounce epilogue,
// small-tile split, packed-w/occ3 (neutral-), chunked launches, full fusion
// (57.8us — occupancy collapse). Do not restructure.
// -----------------------------------------------------------------------------
__global__ __launch_bounds__(256, 2) void qkv_kernel(
    const float* __restrict__ x,
    const float* __restrict__ wq,
    const float* __restrict__ wk,
    const float* __restrict__ wv)
{
    __shared__ float xs[CIN * WWN];            // 12 KB
    __shared__ float wqs[CON * 33];            // padded stride 33
    __shared__ float wks[CON * 33];
    __shared__ float wvs[CON * 33];

    const int h   = blockIdx.x;
    const int bg  = blockIdx.y;                // b*G + g
    const int g   = bg & (GG - 1);
    const int tid = threadIdx.x;

    // Stage x row with float4 loads: x[bg*32 + i][h][w]
    const float* xbase = x + (size_t)bg * CIN * HWSZ + (size_t)h * WWN;
    #pragma unroll
    for (int idx = tid; idx < CIN * (WWN / 4); idx += 256) {
        int i  = idx / (WWN / 4);
        int w4 = idx - i * (WWN / 4);
        reinterpret_cast<float4*>(xs)[i * (WWN / 4) + w4] =
            reinterpret_cast<const float4*>(xbase + (size_t)i * HWSZ)[w4];
    }
    // Stage weights of this group (wq pre-scaled by log2 e)
    const float L2E = 1.44269504088896341f;
    const float* wqg = wq + (size_t)g * CON * CIN;
    const float* wkg = wk + (size_t)g * CON * CIN;
    const float* wvg = wv + (size_t)g * CON * CIN;
    #pragma unroll
    for (int idx = tid; idx < CON * CIN; idx += 256) {
        int o = idx >> 5;
        int i = idx & 31;
        wqs[o * 33 + i] = wqg[idx] * L2E;
        wks[o * 33 + i] = wkg[idx];
        wvs[o * 33 + i] = wvg[idx];
    }
    __syncthreads();

    const int o    = tid >> 3;            // 0..31 output channel
    const int wseg = (tid & 7) * 12;      // 12 consecutive w positions

    float aq[12], ak[12], av[12];
    #pragma unroll
    for (int u = 0; u < 12; u++) { aq[u] = 0.f; ak[u] = 0.f; av[u] = 0.f; }

    #pragma unroll 8
    for (int i = 0; i < CIN; i++) {
        const float wqv = wqs[o * 33 + i];
        const float wkv = wks[o * 33 + i];
        const float wvv = wvs[o * 33 + i];
        const float4* xv = reinterpret_cast<const float4*>(&xs[i * WWN + wseg]);
        float4 x0 = xv[0], x1 = xv[1], x2 = xv[2];
        float xr[12] = { x0.x, x0.y, x0.z, x0.w,
                         x1.x, x1.y, x1.z, x1.w,
                         x2.x, x2.y, x2.z, x2.w };
        #pragma unroll
        for (int u = 0; u < 12; u++) {
            aq[u] = fmaf(xr[u], wqv, aq[u]);
            ak[u] = fmaf(xr[u], wkv, ak[u]);
            av[u] = fmaf(xr[u], wvv, av[u]);
        }
    }

    const size_t obase = (size_t)(bg * CON + o) * HWSZ + (size_t)h * WWN + wseg;
    float4* qo = reinterpret_cast<float4*>(&g_q[obase]);
    float4* ko = reinterpret_cast<float4*>(&g_k[obase]);
    float4* vo = reinterpret_cast<float4*>(&g_v[obase]);
    #pragma unroll
    for (int u = 0; u < 3; u++) {
        qo[u] = make_float4(aq[4*u], aq[4*u+1], aq[4*u+2], aq[4*u+3]);
        ko[u] = make_float4(ak[4*u], ak[4*u+1], ak[4*u+2], ak[4*u+3]);
        vo[u] = make_float4(av[4*u], av[4*u+1], av[4*u+2], av[4*u+3]);
    }
}

// -----------------------------------------------------------------------------
// Kernel B: per-channel 5x5 windowed softmax with reflect indexing.
// R10 proven shape (16.8us): 256 threads (8 tx x 32 ty), 4 consecutive w
// outputs/thread, LDS.128 halo stride 44, pure-MUFU single-pass softmax.
// Changes vs R10: q arrives pre-scaled by log2(e) (no per-thread FMULs), and
// the q4 global load is hoisted above halo staging so its DRAM latency
// overlaps the staging loop instead of following the barrier.
// Ledger of regressions: 128-thread/8-output tiles (21.0us), hybrid poly-exp
// (19.9us), chunked launches (49.7us), fused single kernel (57.8us).
// -----------------------------------------------------------------------------
__device__ __forceinline__ int refl(int i, int n) {
    return i < 0 ? -i : (i >= n ? 2 * n - 2 - i : i);
}

__device__ __forceinline__ float ex2(float x) {
    float y;
    asm("ex2.approx.ftz.f32 %0, %1;" : "=f"(y) : "f"(x));
    return y;
}

#define HALO 36
#define HSTR 44

__global__ __launch_bounds__(256) void attn_kernel(float* __restrict__ out)
{
    __shared__ __align__(16) float ks[HALO * HSTR];   // 6.3 KB
    __shared__ __align__(16) float vs[HALO * HSTR];

    const int ch  = blockIdx.z;               // 0..255 = b*128 + channel
    const int h0  = blockIdx.y * 32;
    const int w0  = blockIdx.x * 32;
    const int tid = threadIdx.x;
    const int tx  = tid & 7;                  // 8 threads across w (4 outputs each)
    const int ty  = tid >> 3;                 // 32 rows

    const size_t cbase = (size_t)ch * HWSZ;
    const int h    = h0 + ty;
    const int wsub = tx * 4;                  // halo column base for this thread
    const size_t pix = (size_t)h * WWN + (w0 + wsub);

    // Hoisted q load (already scaled by log2 e in qkv) — overlaps staging.
    const float4 q4 = *reinterpret_cast<const float4*>(&g_q[cbase + pix]);

    // Stage k/v halos (36x36 window, reflect at global borders).
    #pragma unroll
    for (int idx = tid; idx < HALO * HALO; idx += 256) {
        int r  = idx / HALO;
        int c  = idx - r * HALO;
        int hh = refl(h0 - 2 + r, HHN);
        int ww = refl(w0 - 2 + c, WWN);
        size_t gi = cbase + (size_t)hh * WWN + ww;
        ks[r * HSTR + c] = g_k[gi];
        vs[r * HSTR + c] = g_v[gi];
    }
    __syncthreads();

    float ql2[4] = { q4.x, q4.y, q4.z, q4.w };

    float num[4] = {0.f, 0.f, 0.f, 0.f};
    float den[4] = {0.f, 0.f, 0.f, 0.f};

    #pragma unroll
    for (int r = 0; r < 5; r++) {
        const float4* kp = reinterpret_cast<const float4*>(&ks[(ty + r) * HSTR + wsub]);
        const float4* vp = reinterpret_cast<const float4*>(&vs[(ty + r) * HSTR + wsub]);
        float4 k0 = kp[0], k1 = kp[1];
        float4 v0 = vp[0], v1 = vp[1];
        float kk[8] = { k0.x, k0.y, k0.z, k0.w, k1.x, k1.y, k1.z, k1.w };
        float vv[8] = { v0.x, v0.y, v0.z, v0.w, v1.x, v1.y, v1.z, v1.w };
        #pragma unroll
        for (int o = 0; o < 4; o++) {
            #pragma unroll
            for (int c = 0; c < 5; c++) {
                float e = ex2(ql2[o] * kk[o + c]);
                den[o] += e;
                num[o] = fmaf(e, vv[o + c], num[o]);
            }
        }
    }

    float4 r4 = make_float4(__fdividef(num[0], den[0]),
                            __fdividef(num[1], den[1]),
                            __fdividef(num[2], den[2]),
                            __fdividef(num[3], den[3]));
    *reinterpret_cast<float4*>(&out[cbase + pix]) = r4;
}

// -----------------------------------------------------------------------------
// Launch: two kernels, single stream (the R10 structure — global best).
// Inputs (metadata order): x, wq, wk, wv — all float32. Output float32.
// -----------------------------------------------------------------------------
extern "C" void kernel_launch(void* const* d_in, const int* in_sizes, int n_in,
                              void* d_out, int out_size)
{
    const float* x  = (const float*)d_in[0];
    const float* wq = (const float*)d_in[1];
    const float* wk = (const float*)d_in[2];
    const float* wv = (const float*)d_in[3];
    float* out = (float*)d_out;

    qkv_kernel<<<dim3(HHN, BB * GG), 256>>>(x, wq, wk, wv);
    attn_kernel<<<dim3(WWN / 32, HHN / 32, BB * CTOT), dim3(256)>>>(out);
}